// round 3
// baseline (speedup 1.0000x reference)
#include <cuda_runtime.h>
#include <math.h>

// ---------------- problem constants ----------------
#define BSZ 256
#define TN  16
#define PN  16
#define NT  4096        // BSZ*TN images
#define PT  256         // PN*TN
#define ALPHA_C 0.5f

// output layout in d_out (tuple flattened in order: xr, mu, cov, Pm)
#define XR_SZ   (NT*1024)            // 4,194,304
#define MU_OFF  XR_SZ
#define MU_SZ   (BSZ*PT)             // 65,536
#define COV_OFF (MU_OFF+MU_SZ)
#define COV_SZ  (BSZ*PT*PT)          // 16,777,216
#define PM_OFF  (COV_OFF+COV_SZ)

// ---------------- scratch (no cudaMalloc allowed) ----------------
__device__ float g_h1[NT*32*16*16];
__device__ float g_h2[NT*32*8*8];
__device__ float g_h3[NT*64*4*4];
__device__ float g_h4[NT*64*2*2];
__device__ float g_h5[NT*64];          // == [256,1024] flat
__device__ float g_Dv[BSZ*4096];
__device__ float g_Bv[BSZ*3840];
__device__ float g_z [BSZ*PT];
__device__ float g_hd[BSZ*1024];       // == [4096,64] flat
__device__ float g_d1[NT*64*2*2];
__device__ float g_d2[NT*64*4*4];
__device__ float g_d3[NT*32*8*8];
__device__ float g_d4[NT*32*16*16];

// ---------------- strided conv (k3,s2,p1) + ReLU ----------------
__global__ void conv_s2_relu(const float* __restrict__ in, const float* __restrict__ w,
                             const float* __restrict__ bias, float* __restrict__ out,
                             int Cin, int Hin, int Cout) {
    int Hout = Hin >> 1;
    int total = NT * Cout * Hout * Hout;
    int idx = blockIdx.x * blockDim.x + threadIdx.x;
    if (idx >= total) return;
    int x = idx % Hout; int r = idx / Hout;
    int y = r % Hout;   r /= Hout;
    int co = r % Cout;  int n = r / Cout;

    float s = bias[co];
    const float* wp = w + co * Cin * 9;
    const float* ip = in + (size_t)n * Cin * Hin * Hin;
    for (int ci = 0; ci < Cin; ci++) {
        const float* ipc = ip + ci * Hin * Hin;
        const float* wpc = wp + ci * 9;
        #pragma unroll
        for (int ky = 0; ky < 3; ky++) {
            int iy = 2*y + ky - 1;
            if (iy < 0 || iy >= Hin) continue;
            #pragma unroll
            for (int kx = 0; kx < 3; kx++) {
                int ix = 2*x + kx - 1;
                if (ix < 0 || ix >= Hin) continue;
                s += ipc[iy*Hin + ix] * wpc[ky*3 + kx];
            }
        }
    }
    out[idx] = fmaxf(s, 0.f);
}

// ---------------- transposed conv (k3,s2,p1,op1) + ELU/sigmoid ----------------
__global__ void convt_s2(const float* __restrict__ in, const float* __restrict__ w,
                         const float* __restrict__ bias, float* __restrict__ out,
                         int Cin, int Hin, int Cout, int act /*0=elu, 1=sigmoid*/) {
    int Hout = Hin * 2;
    int total = NT * Cout * Hout * Hout;
    int idx = blockIdx.x * blockDim.x + threadIdx.x;
    if (idx >= total) return;
    int x = idx % Hout; int r = idx / Hout;
    int y = r % Hout;   r /= Hout;
    int co = r % Cout;  int n = r / Cout;

    float s = bias[co];
    const float* ip = in + (size_t)n * Cin * Hin * Hin;
    #pragma unroll
    for (int ky = 0; ky < 3; ky++) {
        int ty = y + 1 - ky;
        if (ty < 0 || (ty & 1)) continue;
        int iy = ty >> 1;
        if (iy >= Hin) continue;
        #pragma unroll
        for (int kx = 0; kx < 3; kx++) {
            int tx = x + 1 - kx;
            if (tx < 0 || (tx & 1)) continue;
            int ix = tx >> 1;
            if (ix >= Hin) continue;
            for (int ci = 0; ci < Cin; ci++) {
                s += ip[(ci*Hin + iy)*Hin + ix] * w[((ci*Cout + co)*3 + ky)*3 + kx];
            }
        }
    }
    if (act) out[idx] = 1.f / (1.f + expf(-s));
    else     out[idx] = (s > 0.f) ? s : expm1f(s);
}

// ---------------- GEMM: C[M,N] = A[M,K] @ B[N,K]^T + bias[N] ----------------
__global__ void gemm_bt64(const float* __restrict__ A, const float* __restrict__ Bm,
                          const float* __restrict__ bias, float* __restrict__ C,
                          int M, int N, int K) {
    __shared__ float As[64][17];
    __shared__ float Bs[64][17];
    int tid = threadIdx.x;
    int tx = tid & 15, ty = tid >> 4;
    int m0 = blockIdx.y * 64, n0 = blockIdx.x * 64;

    float acc[4][4] = {};
    for (int k0 = 0; k0 < K; k0 += 16) {
        #pragma unroll
        for (int l = 0; l < 4; l++) {
            int e = tid + l * 256;
            int mm = e >> 4, kk = e & 15;
            As[mm][kk] = A[(size_t)(m0 + mm) * K + k0 + kk];
            Bs[mm][kk] = Bm[(size_t)(n0 + mm) * K + k0 + kk];
        }
        __syncthreads();
        #pragma unroll
        for (int k = 0; k < 16; k++) {
            float a[4], b[4];
            #pragma unroll
            for (int r = 0; r < 4; r++) a[r] = As[ty*4 + r][k];
            #pragma unroll
            for (int c = 0; c < 4; c++) b[c] = Bs[tx*4 + c][k];
            #pragma unroll
            for (int r = 0; r < 4; r++)
                #pragma unroll
                for (int c = 0; c < 4; c++)
                    acc[r][c] += a[r] * b[c];
        }
        __syncthreads();
    }
    #pragma unroll
    for (int r = 0; r < 4; r++)
        #pragma unroll
        for (int c = 0; c < 4; c++)
            C[(size_t)(m0 + ty*4 + r) * N + n0 + tx*4 + c] = acc[r][c] + bias[n0 + tx*4 + c];
}

// ---------------- Pm builder (raw, unsymmetrized — matches build_tridiag) ----------------
__global__ void build_pm(const float* __restrict__ Dv, const float* __restrict__ Bv,
                         float* __restrict__ Pm) {
    size_t idx = (size_t)blockIdx.x * blockDim.x + threadIdx.x;
    size_t total = (size_t)BSZ * PT * PT;
    if (idx >= total) return;
    int c = idx & 255;
    int r = (idx >> 8) & 255;
    int b = idx >> 16;
    int t = r >> 4, i = r & 15, s = c >> 4, j = c & 15;
    float v = 0.f;
    if (t == s)          v = Dv[b*4096 + t*256 + i*16 + j] + (i == j ? ALPHA_C : 0.f);
    else if (t == s + 1) v = Bv[b*3840 + s*256 + i*16 + j];
    else if (s == t + 1) v = Bv[b*3840 + t*256 + j*16 + i];
    Pm[idx] = v;
}

// ---------------- block-tridiagonal Cholesky + L^{-1} + z ----------------
// One CTA (256 threads) per batch sample. Exploits block-bidiagonal structure of L:
//   L_t = chol(D'_t - M_t M_t^T),  M_t = B_{t-1} L_{t-1}^{-T}
//   cov row t:  X[t][s] = -(L_t^{-1} M_t) X[t-1][s],  X[t][t] = L_t^{-1}
// NOTE: jnp.linalg.cholesky -> lax.linalg.cholesky(symmetrize_input=True):
// it factorizes (Pm + Pm^T)/2. Off-diagonal blocks of Pm are an exact transpose
// pair, so only the diagonal blocks change: use (D + D^T)/2, NOT the lower pick.
__global__ void chol_cov_z(const float* __restrict__ Dv, const float* __restrict__ Bv,
                           const float* __restrict__ mu, const float* __restrict__ eps,
                           float* __restrict__ cov, float* __restrict__ z) {
    int b = blockIdx.x;
    int tid = threadIdx.x;
    int i = tid >> 4, j = tid & 15;

    __shared__ float A[16][16];
    __shared__ float Linv[16][16];
    __shared__ float LinvP[16][16];
    __shared__ float Mb[16][16];
    __shared__ float W[16][16];
    __shared__ float rowbuf[2][16*256];
    __shared__ float epss[256];

    epss[tid] = eps[b*256 + tid];

    float* prev = rowbuf[0];
    float* cur  = rowbuf[1];

    for (int t = 0; t < 16; t++) {
        const float* Dp = Dv + b*4096 + t*256;
        float a = 0.5f * (Dp[i*16 + j] + Dp[j*16 + i]);   // symmetrize_input=True
        if (i == j) a += ALPHA_C;
        __syncthreads();               // protect A/Mb/W from previous iteration readers
        A[i][j] = a;
        __syncthreads();

        if (t > 0) {
            const float* Bp = Bv + b*3840 + (t-1)*256;
            float s = 0.f;
            #pragma unroll
            for (int k = 0; k < 16; k++) s += Bp[i*16 + k] * LinvP[j][k];
            Mb[i][j] = s;
            __syncthreads();
            float u = 0.f;
            #pragma unroll
            for (int k = 0; k < 16; k++) u += Mb[i][k] * Mb[j][k];
            A[i][j] -= u;
            __syncthreads();
        }

        // in-place Cholesky (lower) of A
        for (int k = 0; k < 16; k++) {
            if (tid == k*16 + k) A[k][k] = sqrtf(A[k][k]);
            __syncthreads();
            if (j == k && i > k) A[i][k] /= A[k][k];
            __syncthreads();
            if (j > k && j <= i) A[i][j] -= A[i][k] * A[j][k];
            __syncthreads();
        }

        // Linv = A_lower^{-1}  (16 threads, one column each; forward substitution)
        if (tid < 16) {
            int c = tid;
            float x[16];
            #pragma unroll
            for (int r = 0; r < 16; r++) x[r] = 0.f;
            x[c] = 1.f / A[c][c];
            for (int r = c + 1; r < 16; r++) {
                float s = 0.f;
                for (int k = c; k < r; k++) s += A[r][k] * x[k];
                x[r] = -s / A[r][r];
            }
            for (int r = 0; r < 16; r++) Linv[r][c] = x[r];
        }
        __syncthreads();

        if (t > 0) {
            float s = 0.f;
            #pragma unroll
            for (int k = 0; k < 16; k++) s += Linv[i][k] * Mb[k][j];
            W[i][j] = s;
            __syncthreads();
            for (int sb = 0; sb < t; sb++) {
                float u = 0.f;
                #pragma unroll
                for (int k = 0; k < 16; k++) u += W[i][k] * prev[sb*256 + k*16 + j];
                cur[sb*256 + i*16 + j] = -u;
            }
        }
        cur[t*256 + i*16 + j] = Linv[i][j];
        __syncthreads();

        // write cov row t (upper part zeroed)
        float* crow = cov + ((size_t)b*256 + t*16 + i) * 256;
        for (int sb = 0; sb < 16; sb++)
            crow[sb*16 + j] = (sb <= t) ? cur[sb*256 + i*16 + j] : 0.f;

        // z[t*16+i] = mu + cov_row . eps
        if (j == 0) {
            float s = 0.f;
            int lim = (t + 1) * 16;
            for (int c = 0; c < lim; c++)
                s += cur[(c >> 4)*256 + i*16 + (c & 15)] * epss[c];
            z[b*256 + t*16 + i] = mu[b*256 + t*16 + i] + s;
        }

        LinvP[i][j] = Linv[i][j];
        __syncthreads();

        float* tmp = prev; prev = cur; cur = tmp;
    }
}

// ---------------- launch ----------------
static inline int blocks_for(long total, int tpb) { return (int)((total + tpb - 1) / tpb); }

extern "C" void kernel_launch(void* const* d_in, const int* in_sizes, int n_in,
                              void* d_out, int out_size) {
    const float* x      = (const float*)d_in[0];
    const float* eps    = (const float*)d_in[1];
    const float* w1  = (const float*)d_in[2];   const float* b1  = (const float*)d_in[3];
    const float* w2  = (const float*)d_in[4];   const float* b2  = (const float*)d_in[5];
    const float* w3  = (const float*)d_in[6];   const float* b3  = (const float*)d_in[7];
    const float* w4  = (const float*)d_in[8];   const float* b4  = (const float*)d_in[9];
    const float* w5  = (const float*)d_in[10];  const float* b5  = (const float*)d_in[11];
    const float* fc_mu_w = (const float*)d_in[12]; const float* fc_mu_b = (const float*)d_in[13];
    const float* fc_D_w  = (const float*)d_in[14]; const float* fc_D_b  = (const float*)d_in[15];
    const float* fc_B_w  = (const float*)d_in[16]; const float* fc_B_b  = (const float*)d_in[17];
    const float* fc_dec_w = (const float*)d_in[18]; const float* fc_dec_b = (const float*)d_in[19];
    const float* wt5 = (const float*)d_in[20];  const float* bt5 = (const float*)d_in[21];
    const float* wt4 = (const float*)d_in[22];  const float* bt4 = (const float*)d_in[23];
    const float* wt3 = (const float*)d_in[24];  const float* bt3 = (const float*)d_in[25];
    const float* wt2 = (const float*)d_in[26];  const float* bt2 = (const float*)d_in[27];
    const float* wt1 = (const float*)d_in[28];  const float* bt1 = (const float*)d_in[29];

    float* out = (float*)d_out;
    float* o_xr  = out;
    float* o_mu  = out + MU_OFF;
    float* o_cov = out + COV_OFF;
    float* o_pm  = out + PM_OFF;

    float *h1,*h2,*h3,*h4,*h5,*Dv,*Bv,*zb,*hd,*d1,*d2,*d3,*d4;
    cudaGetSymbolAddress((void**)&h1, g_h1);
    cudaGetSymbolAddress((void**)&h2, g_h2);
    cudaGetSymbolAddress((void**)&h3, g_h3);
    cudaGetSymbolAddress((void**)&h4, g_h4);
    cudaGetSymbolAddress((void**)&h5, g_h5);
    cudaGetSymbolAddress((void**)&Dv, g_Dv);
    cudaGetSymbolAddress((void**)&Bv, g_Bv);
    cudaGetSymbolAddress((void**)&zb, g_z);
    cudaGetSymbolAddress((void**)&hd, g_hd);
    cudaGetSymbolAddress((void**)&d1, g_d1);
    cudaGetSymbolAddress((void**)&d2, g_d2);
    cudaGetSymbolAddress((void**)&d3, g_d3);
    cudaGetSymbolAddress((void**)&d4, g_d4);

    const int TPB = 256;

    // ---- encoder ----
    conv_s2_relu<<<blocks_for((long)NT*32*16*16, TPB), TPB>>>(x,  w1, b1, h1, 1,  32, 32);
    conv_s2_relu<<<blocks_for((long)NT*32*8*8,   TPB), TPB>>>(h1, w2, b2, h2, 32, 16, 32);
    conv_s2_relu<<<blocks_for((long)NT*64*4*4,   TPB), TPB>>>(h2, w3, b3, h3, 32, 8,  64);
    conv_s2_relu<<<blocks_for((long)NT*64*2*2,   TPB), TPB>>>(h3, w4, b4, h4, 64, 4,  64);
    conv_s2_relu<<<blocks_for((long)NT*64,       TPB), TPB>>>(h4, w5, b5, h5, 64, 2,  64);

    // ---- FC heads: h5 is [256,1024] flat ----
    { dim3 g(256/64, 256/64);  gemm_bt64<<<g, 256>>>(h5, fc_mu_w, fc_mu_b, o_mu, 256, 256, 1024); }
    { dim3 g(4096/64, 256/64); gemm_bt64<<<g, 256>>>(h5, fc_D_w,  fc_D_b,  Dv,   256, 4096, 1024); }
    { dim3 g(3840/64, 256/64); gemm_bt64<<<g, 256>>>(h5, fc_B_w,  fc_B_b,  Bv,   256, 3840, 1024); }

    // ---- Pm output ----
    build_pm<<<blocks_for((long)BSZ*PT*PT, TPB), TPB>>>(Dv, Bv, o_pm);

    // ---- Cholesky + cov + z ----
    chol_cov_z<<<BSZ, 256>>>(Dv, Bv, o_mu, eps, o_cov, zb);

    // ---- decoder FC: hd [256,1024] == [4096,64,1,1] ----
    { dim3 g(1024/64, 256/64); gemm_bt64<<<g, 256>>>(zb, fc_dec_w, fc_dec_b, hd, 256, 1024, 256); }

    // ---- decoder transposed convs ----
    convt_s2<<<blocks_for((long)NT*64*2*2,   TPB), TPB>>>(hd, wt5, bt5, d1, 64, 1,  64, 0);
    convt_s2<<<blocks_for((long)NT*64*4*4,   TPB), TPB>>>(d1, wt4, bt4, d2, 64, 2,  64, 0);
    convt_s2<<<blocks_for((long)NT*32*8*8,   TPB), TPB>>>(d2, wt3, bt3, d3, 64, 4,  32, 0);
    convt_s2<<<blocks_for((long)NT*32*16*16, TPB), TPB>>>(d3, wt2, bt2, d4, 32, 8,  32, 0);
    convt_s2<<<blocks_for((long)NT*1*32*32,  TPB), TPB>>>(d4, wt1, bt1, o_xr, 32, 16, 1, 1);
}

// round 6
// speedup vs baseline: 4.8860x; 4.8860x over previous
#include <cuda_runtime.h>
#include <math.h>

// ---------------- problem constants ----------------
#define BSZ 256
#define TN  16
#define PN  16
#define NT  4096        // BSZ*TN images
#define PT  256         // PN*TN
#define ALPHA_C 0.5f

// output layout in d_out (tuple flattened in order: xr, mu, cov, Pm)
#define XR_SZ   (NT*1024)
#define MU_OFF  XR_SZ
#define MU_SZ   (BSZ*PT)
#define COV_OFF (MU_OFF+MU_SZ)
#define COV_SZ  (BSZ*PT*PT)
#define PM_OFF  (COV_OFF+COV_SZ)

// ---------------- scratch ----------------
__device__ float g_h1[NT*32*16*16];
__device__ float g_h2[NT*32*8*8];
__device__ float g_h3[NT*64*4*4];
__device__ float g_h4[NT*64*2*2];
__device__ float g_h5[NT*64];
__device__ float g_Dv[BSZ*4096];
__device__ float g_Bv[BSZ*3840];
__device__ float g_z [BSZ*PT];
__device__ float g_hd[BSZ*1024];
__device__ float g_d1[NT*64*2*2];
__device__ float g_d2[NT*64*4*4];
__device__ float g_d3[NT*32*8*8];
__device__ float g_d4[NT*32*16*16];
// packed decoder weights (per-parity, co-major)
__device__ float g_wp5[64*64*9];
__device__ float g_wp4[64*64*9];
__device__ float g_wp3[64*32*9];
__device__ float g_wp2[32*32*9];
__device__ float g_wp1[32*1*9];

// =================================================================
// Encoder conv (k3,s2,p1) + ReLU as implicit GEMM.
// M=Cout rows, N=NT*Hout^2 pixel cols, K=Cin*9 (stepped CB channels at a time).
// =================================================================
template<int CIN,int HIN,int COUT,int CB,int BM,int BN,int TM,int TN_>
__global__ void enc_conv(const float* __restrict__ in, const float* __restrict__ w,
                         const float* __restrict__ bias, float* __restrict__ out) {
    const int H  = HIN/2;
    const int H2 = H*H;
    const int BK = 9*CB;
    __shared__ float As[BK][BM];
    __shared__ float Bs[BK][BN+4];
    const int tid = threadIdx.x;
    const int px0 = blockIdx.x * BN;
    const int MT  = BM/TM;
    const int tidm = tid % MT, tidn = tid / MT;

    float acc[TM][TN_] = {};

    for (int c0 = 0; c0 < CIN; c0 += CB) {
        // stage weights
        for (int e = tid; e < BK*BM; e += 256) {
            int k = e / BM, co = e % BM;
            int cl = k / 9, tap = k - 9*cl;
            As[k][co] = w[(co*CIN + c0 + cl)*9 + tap];
        }
        // stage im2col patch tile
        for (int e = tid; e < BK*BN; e += 256) {
            int k = e / BN, col = e % BN;
            int cl = k / 9, tap = k - 9*cl;
            int ky = tap/3, kx = tap - 3*(tap/3);
            int px = px0 + col;
            int n   = px / H2;
            int rem = px - n*H2;
            int y = rem / H, x = rem - (rem/H)*H;
            int iy = 2*y + ky - 1, ix = 2*x + kx - 1;
            float v = 0.f;
            if ((unsigned)iy < (unsigned)HIN && (unsigned)ix < (unsigned)HIN)
                v = in[(((size_t)n*CIN + c0 + cl)*HIN + iy)*HIN + ix];
            Bs[k][col] = v;
        }
        __syncthreads();
        #pragma unroll
        for (int k = 0; k < BK; k++) {
            float a[TM], b[TN_];
            #pragma unroll
            for (int r = 0; r < TM; r++) a[r] = As[k][tidm*TM + r];
            #pragma unroll
            for (int c = 0; c < TN_; c++) b[c] = Bs[k][tidn*TN_ + c];
            #pragma unroll
            for (int r = 0; r < TM; r++)
                #pragma unroll
                for (int c = 0; c < TN_; c++)
                    acc[r][c] += a[r] * b[c];
        }
        __syncthreads();
    }
    #pragma unroll
    for (int r = 0; r < TM; r++) {
        int co = tidm*TM + r;
        float bb = bias[co];
        #pragma unroll
        for (int c = 0; c < TN_; c++) {
            int px = px0 + tidn*TN_ + c;
            int n = px / H2, rem = px - (px/H2)*H2;
            out[((size_t)n*COUT + co)*H2 + rem] = fmaxf(acc[r][c] + bb, 0.f);
        }
    }
}

// =================================================================
// Decoder weight pack: per-parity, co-major.
// parity p = py*2+px; py class: ky==1 -> py=0, ky in {0,2} -> py=1 (same x).
// =================================================================
__global__ void pack_wt(const float* __restrict__ w, float* __restrict__ wp,
                        int CIN, int COUT) {
    int idx = blockIdx.x * blockDim.x + threadIdx.x;
    int total = CIN*COUT*9;
    if (idx >= total) return;
    int kx = idx % 3; int r = idx / 3;
    int ky = r % 3;   r /= 3;
    int co = r % COUT; int ci = r / COUT;
    int py = (ky != 1), px = (kx != 1);
    int p = py*2 + px;
    int ty = (ky == 2) ? 1 : 0;
    int tx = (kx == 2) ? 1 : 0;
    int ntx = px ? 2 : 1;
    int ntaps = (py ? 2 : 1) * ntx;
    int K = CIN * ntaps;
    const int cum[4] = {0, 1, 3, 5};
    int off = COUT*CIN*cum[p];
    wp[off + co*K + ci*ntaps + ty*ntx + tx] = w[((ci*COUT + co)*3 + ky)*3 + kx];
}

// =================================================================
// Decoder transposed conv (k3,s2,p1,op1) via parity decomposition.
// blockIdx.y = parity. Input HI x HI -> output 2HI x 2HI.
// ACT: 0 = ELU, 1 = sigmoid.
// =================================================================
template<int CIN,int HI,int COUT,int BM,int BN,int TM,int TN_,int ACT>
__global__ void dec_convt(const float* __restrict__ in, const float* __restrict__ wp,
                          const float* __restrict__ bias, float* __restrict__ out) {
    const int HO  = 2*HI;
    const int HI2 = HI*HI;
    const int BK = 16;
    __shared__ float As[BK][BM];
    __shared__ float Bs[BK][BN+4];
    const int tid = threadIdx.x;
    const int par = blockIdx.y;
    const int py = par >> 1, pxp = par & 1;
    const int sh = py + pxp;          // ntaps = 1<<sh
    const int ntaps = 1 << sh;
    const int ntxm1 = pxp;            // ntx-1
    const int K = CIN << sh;
    const int cum[4] = {0, 1, 3, 5};
    const float* wq = wp + (size_t)COUT*CIN*cum[par];

    const int pxl0 = blockIdx.x * BN;
    const int MT = BM/TM;
    const int tidm = tid % MT, tidn = tid / MT;

    float acc[TM][TN_] = {};

    for (int k0 = 0; k0 < K; k0 += BK) {
        for (int e = tid; e < BK*BM; e += 256) {
            int k = e / BM, co = e % BM;
            As[k][co] = wq[co*K + k0 + k];
        }
        for (int e = tid; e < BK*BN; e += 256) {
            int kk = e / BN, col = e % BN;
            int k = k0 + kk;
            int ci = k >> sh;
            int t  = k & (ntaps - 1);
            int ty = t >> pxp;
            int tx = t & ntxm1;
            int dy = (py && ty == 0) ? 1 : 0;
            int dx = (pxp && tx == 0) ? 1 : 0;
            int pxl = pxl0 + col;
            int n   = pxl / HI2;
            int rem = pxl - n*HI2;
            int yi = rem / HI, xi = rem - (rem/HI)*HI;
            int iy = yi + dy, ix = xi + dx;
            float v = 0.f;
            if (iy < HI && ix < HI)
                v = in[(((size_t)n*CIN + ci)*HI + iy)*HI + ix];
            Bs[kk][col] = v;
        }
        __syncthreads();
        #pragma unroll
        for (int k = 0; k < BK; k++) {
            float a[TM], b[TN_];
            #pragma unroll
            for (int r = 0; r < TM; r++) a[r] = As[k][tidm*TM + r];
            #pragma unroll
            for (int c = 0; c < TN_; c++) b[c] = Bs[k][tidn*TN_ + c];
            #pragma unroll
            for (int r = 0; r < TM; r++)
                #pragma unroll
                for (int c = 0; c < TN_; c++)
                    acc[r][c] += a[r] * b[c];
        }
        __syncthreads();
    }
    #pragma unroll
    for (int r = 0; r < TM; r++) {
        int co = tidm*TM + r;
        float bb = bias[co];
        #pragma unroll
        for (int c = 0; c < TN_; c++) {
            int pxl = pxl0 + tidn*TN_ + c;
            int n   = pxl / HI2;
            int rem = pxl - n*HI2;
            int yi = rem / HI, xi = rem - (rem/HI)*HI;
            float s = acc[r][c] + bb;
            float o;
            if (ACT) o = 1.f / (1.f + expf(-s));
            else     o = (s > 0.f) ? s : expm1f(s);
            out[(((size_t)n*COUT + co)*HO + 2*yi + py)*HO + 2*xi + pxp] = o;
        }
    }
}

// ---------------- GEMM: C[M,N] = A[M,K] @ B[N,K]^T + bias[N] ----------------
__global__ void gemm_bt64(const float* __restrict__ A, const float* __restrict__ Bm,
                          const float* __restrict__ bias, float* __restrict__ C,
                          int M, int N, int K) {
    __shared__ float As[64][17];
    __shared__ float Bs[64][17];
    int tid = threadIdx.x;
    int tx = tid & 15, ty = tid >> 4;
    int m0 = blockIdx.y * 64, n0 = blockIdx.x * 64;

    float acc[4][4] = {};
    for (int k0 = 0; k0 < K; k0 += 16) {
        #pragma unroll
        for (int l = 0; l < 4; l++) {
            int e = tid + l * 256;
            int mm = e >> 4, kk = e & 15;
            As[mm][kk] = A[(size_t)(m0 + mm) * K + k0 + kk];
            Bs[mm][kk] = Bm[(size_t)(n0 + mm) * K + k0 + kk];
        }
        __syncthreads();
        #pragma unroll
        for (int k = 0; k < 16; k++) {
            float a[4], b[4];
            #pragma unroll
            for (int r = 0; r < 4; r++) a[r] = As[ty*4 + r][k];
            #pragma unroll
            for (int c = 0; c < 4; c++) b[c] = Bs[tx*4 + c][k];
            #pragma unroll
            for (int r = 0; r < 4; r++)
                #pragma unroll
                for (int c = 0; c < 4; c++)
                    acc[r][c] += a[r] * b[c];
        }
        __syncthreads();
    }
    #pragma unroll
    for (int r = 0; r < 4; r++)
        #pragma unroll
        for (int c = 0; c < 4; c++)
            C[(size_t)(m0 + ty*4 + r) * N + n0 + tx*4 + c] = acc[r][c] + bias[n0 + tx*4 + c];
}

// ---------------- Pm builder (raw, unsymmetrized) — float4 stores ----------------
__global__ void build_pm4(const float* __restrict__ Dv, const float* __restrict__ Bv,
                          float4* __restrict__ Pm) {
    size_t idx = (size_t)blockIdx.x * blockDim.x + threadIdx.x;
    size_t total = (size_t)BSZ * PT * 64;   // rows x col-quads
    if (idx >= total) return;
    int c4 = idx & 63;
    int r  = (idx >> 6) & 255;
    int b  = idx >> 14;
    int t = r >> 4, i = r & 15;
    int s = c4 >> 2, j0 = (c4 & 3) * 4;
    float4 v = {0.f, 0.f, 0.f, 0.f};
    if (t == s) {
        const float4* dp = (const float4*)(Dv + b*4096 + t*256 + i*16 + j0);
        v = *dp;
        if (i >= j0 && i < j0+4) { (&v.x)[i - j0] += ALPHA_C; }
    } else if (t == s + 1) {
        v = *(const float4*)(Bv + b*3840 + s*256 + i*16 + j0);
    } else if (s == t + 1) {
        const float* bp = Bv + b*3840 + t*256 + i;
        v.x = bp[(j0+0)*16]; v.y = bp[(j0+1)*16];
        v.z = bp[(j0+2)*16]; v.w = bp[(j0+3)*16];
    }
    Pm[idx] = v;
}

// ---------------- block-tridiagonal Cholesky + L^{-1} + z ----------------
__global__ void chol_cov_z(const float* __restrict__ Dv, const float* __restrict__ Bv,
                           const float* __restrict__ mu, const float* __restrict__ eps,
                           float* __restrict__ cov, float* __restrict__ z) {
    int b = blockIdx.x;
    int tid = threadIdx.x;
    int i = tid >> 4, j = tid & 15;

    __shared__ float A[16][16];
    __shared__ float Linv[16][16];
    __shared__ float LinvP[16][16];
    __shared__ float Mb[16][16];
    __shared__ float W[16][16];
    __shared__ float rowbuf[2][16*256];
    __shared__ float epss[256];

    epss[tid] = eps[b*256 + tid];

    float* prev = rowbuf[0];
    float* cur  = rowbuf[1];

    for (int t = 0; t < 16; t++) {
        const float* Dp = Dv + b*4096 + t*256;
        float a = 0.5f * (Dp[i*16 + j] + Dp[j*16 + i]);   // symmetrize_input=True
        if (i == j) a += ALPHA_C;
        __syncthreads();
        A[i][j] = a;
        __syncthreads();

        if (t > 0) {
            const float* Bp = Bv + b*3840 + (t-1)*256;
            float s = 0.f;
            #pragma unroll
            for (int k = 0; k < 16; k++) s += Bp[i*16 + k] * LinvP[j][k];
            Mb[i][j] = s;
            __syncthreads();
            float u = 0.f;
            #pragma unroll
            for (int k = 0; k < 16; k++) u += Mb[i][k] * Mb[j][k];
            A[i][j] -= u;
            __syncthreads();
        }

        for (int k = 0; k < 16; k++) {
            if (tid == k*16 + k) A[k][k] = sqrtf(A[k][k]);
            __syncthreads();
            if (j == k && i > k) A[i][k] /= A[k][k];
            __syncthreads();
            if (j > k && j <= i) A[i][j] -= A[i][k] * A[j][k];
            __syncthreads();
        }

        if (tid < 16) {
            int c = tid;
            float x[16];
            #pragma unroll
            for (int r = 0; r < 16; r++) x[r] = 0.f;
            x[c] = 1.f / A[c][c];
            for (int r = c + 1; r < 16; r++) {
                float s = 0.f;
                for (int k = c; k < r; k++) s += A[r][k] * x[k];
                x[r] = -s / A[r][r];
            }
            for (int r = 0; r < 16; r++) Linv[r][c] = x[r];
        }
        __syncthreads();

        if (t > 0) {
            float s = 0.f;
            #pragma unroll
            for (int k = 0; k < 16; k++) s += Linv[i][k] * Mb[k][j];
            W[i][j] = s;
            __syncthreads();
            for (int sb = 0; sb < t; sb++) {
                float u = 0.f;
                #pragma unroll
                for (int k = 0; k < 16; k++) u += W[i][k] * prev[sb*256 + k*16 + j];
                cur[sb*256 + i*16 + j] = -u;
            }
        }
        cur[t*256 + i*16 + j] = Linv[i][j];
        __syncthreads();

        float* crow = cov + ((size_t)b*256 + t*16 + i) * 256;
        for (int sb = 0; sb < 16; sb++)
            crow[sb*16 + j] = (sb <= t) ? cur[sb*256 + i*16 + j] : 0.f;

        if (j == 0) {
            float s = 0.f;
            int lim = (t + 1) * 16;
            for (int c = 0; c < lim; c++)
                s += cur[(c >> 4)*256 + i*16 + (c & 15)] * epss[c];
            z[b*256 + t*16 + i] = mu[b*256 + t*16 + i] + s;
        }

        LinvP[i][j] = Linv[i][j];
        __syncthreads();

        float* tmp = prev; prev = cur; cur = tmp;
    }
}

// ---------------- launch ----------------
static inline int blocks_for(long total, int tpb) { return (int)((total + tpb - 1) / tpb); }

extern "C" void kernel_launch(void* const* d_in, const int* in_sizes, int n_in,
                              void* d_out, int out_size) {
    const float* x      = (const float*)d_in[0];
    const float* eps    = (const float*)d_in[1];
    const float* w1  = (const float*)d_in[2];   const float* b1  = (const float*)d_in[3];
    const float* w2  = (const float*)d_in[4];   const float* b2  = (const float*)d_in[5];
    const float* w3  = (const float*)d_in[6];   const float* b3  = (const float*)d_in[7];
    const float* w4  = (const float*)d_in[8];   const float* b4  = (const float*)d_in[9];
    const float* w5  = (const float*)d_in[10];  const float* b5  = (const float*)d_in[11];
    const float* fc_mu_w = (const float*)d_in[12]; const float* fc_mu_b = (const float*)d_in[13];
    const float* fc_D_w  = (const float*)d_in[14]; const float* fc_D_b  = (const float*)d_in[15];
    const float* fc_B_w  = (const float*)d_in[16]; const float* fc_B_b  = (const float*)d_in[17];
    const float* fc_dec_w = (const float*)d_in[18]; const float* fc_dec_b = (const float*)d_in[19];
    const float* wt5 = (const float*)d_in[20];  const float* bt5 = (const float*)d_in[21];
    const float* wt4 = (const float*)d_in[22];  const float* bt4 = (const float*)d_in[23];
    const float* wt3 = (const float*)d_in[24];  const float* bt3 = (const float*)d_in[25];
    const float* wt2 = (const float*)d_in[26];  const float* bt2 = (const float*)d_in[27];
    const float* wt1 = (const float*)d_in[28];  const float* bt1 = (const float*)d_in[29];

    float* out = (float*)d_out;
    float* o_xr  = out;
    float* o_mu  = out + MU_OFF;
    float* o_cov = out + COV_OFF;
    float* o_pm  = out + PM_OFF;

    float *h1,*h2,*h3,*h4,*h5,*Dv,*Bv,*zb,*hd,*d1,*d2,*d3,*d4;
    float *wp5,*wp4,*wp3,*wp2,*wp1;
    cudaGetSymbolAddress((void**)&h1, g_h1);
    cudaGetSymbolAddress((void**)&h2, g_h2);
    cudaGetSymbolAddress((void**)&h3, g_h3);
    cudaGetSymbolAddress((void**)&h4, g_h4);
    cudaGetSymbolAddress((void**)&h5, g_h5);
    cudaGetSymbolAddress((void**)&Dv, g_Dv);
    cudaGetSymbolAddress((void**)&Bv, g_Bv);
    cudaGetSymbolAddress((void**)&zb, g_z);
    cudaGetSymbolAddress((void**)&hd, g_hd);
    cudaGetSymbolAddress((void**)&d1, g_d1);
    cudaGetSymbolAddress((void**)&d2, g_d2);
    cudaGetSymbolAddress((void**)&d3, g_d3);
    cudaGetSymbolAddress((void**)&d4, g_d4);
    cudaGetSymbolAddress((void**)&wp5, g_wp5);
    cudaGetSymbolAddress((void**)&wp4, g_wp4);
    cudaGetSymbolAddress((void**)&wp3, g_wp3);
    cudaGetSymbolAddress((void**)&wp2, g_wp2);
    cudaGetSymbolAddress((void**)&wp1, g_wp1);

    const int TPB = 256;

    // ---- encoder (implicit GEMM convs) ----
    enc_conv<1, 32, 32, 1, 32, 128, 4, 4><<<8192, 256>>>(x,  w1, b1, h1);
    enc_conv<32,16, 32, 2, 32, 128, 4, 4><<<2048, 256>>>(h1, w2, b2, h2);
    enc_conv<32, 8, 64, 2, 64, 128, 4, 8><<< 512, 256>>>(h2, w3, b3, h3);
    enc_conv<64, 4, 64, 2, 64, 128, 4, 8><<< 128, 256>>>(h3, w4, b4, h4);
    enc_conv<64, 2, 64, 2, 64, 128, 4, 8><<<  32, 256>>>(h4, w5, b5, h5);

    // ---- FC heads ----
    { dim3 g(256/64, 256/64);  gemm_bt64<<<g, 256>>>(h5, fc_mu_w, fc_mu_b, o_mu, 256, 256, 1024); }
    { dim3 g(4096/64, 256/64); gemm_bt64<<<g, 256>>>(h5, fc_D_w,  fc_D_b,  Dv,   256, 4096, 1024); }
    { dim3 g(3840/64, 256/64); gemm_bt64<<<g, 256>>>(h5, fc_B_w,  fc_B_b,  Bv,   256, 3840, 1024); }

    // ---- Pm output ----
    build_pm4<<<blocks_for((long)BSZ*PT*64, TPB), TPB>>>(Dv, Bv, (float4*)o_pm);

    // ---- Cholesky + cov + z ----
    chol_cov_z<<<BSZ, 256>>>(Dv, Bv, o_mu, eps, o_cov, zb);

    // ---- decoder FC ----
    { dim3 g(1024/64, 256/64); gemm_bt64<<<g, 256>>>(zb, fc_dec_w, fc_dec_b, hd, 256, 1024, 256); }

    // ---- pack decoder weights per-parity ----
    pack_wt<<<blocks_for(64*64*9, TPB), TPB>>>(wt5, wp5, 64, 64);
    pack_wt<<<blocks_for(64*64*9, TPB), TPB>>>(wt4, wp4, 64, 64);
    pack_wt<<<blocks_for(64*32*9, TPB), TPB>>>(wt3, wp3, 64, 32);
    pack_wt<<<blocks_for(32*32*9, TPB), TPB>>>(wt2, wp2, 32, 32);
    pack_wt<<<blocks_for(32*1*9,  TPB), TPB>>>(wt1, wp1, 32, 1);

    // ---- decoder transposed convs (parity-decomposed implicit GEMM) ----
    { dim3 g(  32, 4); dec_convt<64, 1, 64, 64, 128, 4, 8, 0><<<g, 256>>>(hd, wp5, bt5, d1); }
    { dim3 g( 128, 4); dec_convt<64, 2, 64, 64, 128, 4, 8, 0><<<g, 256>>>(d1, wp4, bt4, d2); }
    { dim3 g( 512, 4); dec_convt<64, 4, 32, 32, 128, 4, 4, 0><<<g, 256>>>(d2, wp3, bt3, d3); }
    { dim3 g(2048, 4); dec_convt<32, 8, 32, 32, 128, 4, 4, 0><<<g, 256>>>(d3, wp2, bt2, d4); }
    { dim3 g(4096, 4); dec_convt<32,16,  1,  1, 256, 1, 1, 1><<<g, 256>>>(d4, wp1, bt1, o_xr); }
}